// round 1
// baseline (speedup 1.0000x reference)
#include <cuda_runtime.h>
#include <math.h>

// ---------------- device scratch (no allocation allowed) ----------------
__device__ __align__(16) float g_v1[256];
__device__ __align__(16) float g_v2[256];
__device__ float g_p1[128];
__device__ float g_p2[128];

#define NEGV (-9000000000000000.0f)

// ---------------- prep: v1 = W@a1, v2 = W@a2, pos1/pos2 -----------------
__global__ void prep_kernel(const float* __restrict__ W, const float* __restrict__ a) {
    __shared__ float v1s[256], v2s[256];
    __shared__ float a1s[256], a2s[256];
    __shared__ double invd[128];
    int t = threadIdx.x;

    a1s[t] = a[t];
    a2s[t] = a[256 + t];
    if (t < 128) invd[t] = pow(10000.0, -(double)(2 * t) / 256.0);
    __syncthreads();

    // v1[t] = sum_o W[t,o] * a1[o], W row-major (256,256) -> contiguous per thread
    float acc1 = 0.f, acc2 = 0.f;
    const float4* Wv = (const float4*)(W + t * 256);
    const float4* A1 = (const float4*)a1s;
    const float4* A2 = (const float4*)a2s;
#pragma unroll 8
    for (int q = 0; q < 64; q++) {
        float4 w = Wv[q];
        float4 b1 = A1[q], b2 = A2[q];
        acc1 += w.x * b1.x + w.y * b1.y + w.z * b1.z + w.w * b1.w;
        acc2 += w.x * b2.x + w.y * b2.y + w.z * b2.z + w.w * b2.w;
    }
    v1s[t] = acc1; v2s[t] = acc2;
    g_v1[t] = acc1; g_v2[t] = acc2;
    __syncthreads();

    // pos1[n] = 1000 * sum_f table(n,f) * v1[f]
    if (t < 128) {
        float p1 = 0.f, p2 = 0.f;
        for (int f = 0; f < 256; f++) {
            float angle = (float)((double)t * invd[f >> 1]);
            float tv = (f & 1) ? cosf(angle) : sinf(angle);
            p1 += tv * v1s[f];
            p2 += tv * v2s[f];
        }
        g_p1[t] = 1000.0f * p1;
        g_p2[t] = 1000.0f * p2;
    }
}

// ---------------- fused main kernel: 1 CTA per batch --------------------
// smem layout (floats): s1[128] s2[128] lt[128] lu[128] red[256] vs[16384]
#define SMEM_FLOATS (128 + 128 + 128 + 128 + 256 + 128 * 128)

__global__ void __launch_bounds__(256) gat_kernel(
    const float* __restrict__ src,
    const float* __restrict__ adj,
    float* __restrict__ out)
{
    extern __shared__ float sm[];
    float* s1s = sm;
    float* s2s = sm + 128;
    float* lt  = sm + 256;
    float* lu  = sm + 384;
    float* red = sm + 512;
    float* vs  = sm + 768;

    const int b   = blockIdx.x;
    const int tid = threadIdx.x;
    const int w   = tid >> 5;
    const int l   = tid & 31;

    // -- phase A: s1[n] = src[b,n,:].v1 + pos1[n]  (8 warps x 16 rows) --
    const float4* v1p = (const float4*)g_v1;
    const float4* v2p = (const float4*)g_v2;
    float4 v1a = v1p[l], v1b = v1p[l + 32];
    float4 v2a = v2p[l], v2b = v2p[l + 32];

    const float4* sbase = (const float4*)(src + (size_t)b * 32768);
#pragma unroll 2
    for (int r = 0; r < 16; r++) {
        int n = w * 16 + r;
        float4 x0 = sbase[n * 64 + l];
        float4 x1 = sbase[n * 64 + 32 + l];
        float acc1 = x0.x * v1a.x + x0.y * v1a.y + x0.z * v1a.z + x0.w * v1a.w
                   + x1.x * v1b.x + x1.y * v1b.y + x1.z * v1b.z + x1.w * v1b.w;
        float acc2 = x0.x * v2a.x + x0.y * v2a.y + x0.z * v2a.z + x0.w * v2a.w
                   + x1.x * v2b.x + x1.y * v2b.y + x1.z * v2b.z + x1.w * v2b.w;
#pragma unroll
        for (int off = 16; off; off >>= 1) {
            acc1 += __shfl_xor_sync(0xFFFFFFFFu, acc1, off);
            acc2 += __shfl_xor_sync(0xFFFFFFFFu, acc2, off);
        }
        if (l == 0) {
            s1s[n] = acc1 + g_p1[n];
            s2s[n] = acc2 + g_p2[n];
        }
    }
    __syncthreads();

    // -- phase B: precompute leaky(t[m]), leaky(u[m]) --
    if (tid < 128) {
        int m = tid;
        float t = s1s[m] + s2s[m];
        lt[m] = (t > 0.f) ? t : 0.2f * t;
        float u = s1s[(2 * m) & 127] + s2s[(2 * m + 1) & 127];
        lu[m] = (u > 0.f) ? u : 0.2f * u;
    }
    __syncthreads();

    // -- phase C: masked values + column max.
    //    thread = (j, h); h=0 handles i in [0,64), h=1 handles i in [64,128).
    const int j = tid & 127;
    const int h = tid >> 7;
    const int base = h * 64;
    const float* adjb = adj + (size_t)b * 16384 + j;

    float mmax = -3.402823466e38f;
    if (h == 0) {
        const int jhi = (j >= 64) ? 1 : 0;
#pragma unroll 8
        for (int ii = 0; ii < 64; ii++) {
            float av = __ldg(adjb + (size_t)ii * 128);
            float val = (av > 0.f) ? lt[2 * ii + jhi] : NEGV;
            vs[ii * 128 + j] = val;
            mmax = fmaxf(mmax, val);
        }
    } else {
        const float cu = lu[j];
#pragma unroll 8
        for (int ii = 0; ii < 64; ii++) {
            float av = __ldg(adjb + (size_t)(64 + ii) * 128);
            float val = (av > 0.f) ? cu : NEGV;
            vs[(64 + ii) * 128 + j] = val;
            mmax = fmaxf(mmax, val);
        }
    }
    red[tid] = mmax;
    __syncthreads();
    const float mf = fmaxf(red[j], red[j + 128]);
    __syncthreads();   // protect red before reuse

    // -- phase D: exp + column sum (exp stored back into vs) --
    float lsum = 0.f;
#pragma unroll 8
    for (int ii = 0; ii < 64; ii++) {
        int i = base + ii;
        float ex = expf(vs[i * 128 + j] - mf);
        vs[i * 128 + j] = ex;
        lsum += ex;
    }
    red[tid] = lsum;
    __syncthreads();
    const float inv = 1.0f / (red[j] + red[j + 128]);

    // -- phase E: normalized write-out (coalesced in j) --
    float* outp = out + (size_t)b * 16384 + j;
#pragma unroll 8
    for (int ii = 0; ii < 64; ii++) {
        int i = base + ii;
        outp[(size_t)i * 128] = vs[i * 128 + j] * inv;
    }
}

// ---------------- launcher ----------------
extern "C" void kernel_launch(void* const* d_in, const int* in_sizes, int n_in,
                              void* d_out, int out_size) {
    const float* src = (const float*)d_in[0];   // (2048,128,256)
    const float* W   = (const float*)d_in[1];   // (256,256)
    const float* a   = (const float*)d_in[2];   // (512,1)
    const float* adj = (const float*)d_in[3];   // (2048,128,128)
    float* out = (float*)d_out;                 // (2048,128,128)

    const int smem_bytes = SMEM_FLOATS * sizeof(float);  // 68608
    cudaFuncSetAttribute(gat_kernel, cudaFuncAttributeMaxDynamicSharedMemorySize, smem_bytes);

    prep_kernel<<<1, 256>>>(W, a);
    gat_kernel<<<2048, 256, smem_bytes>>>(src, adj, out);
}

// round 2
// speedup vs baseline: 1.5183x; 1.5183x over previous
#include <cuda_runtime.h>
#include <math.h>

// ---------------- device scratch (no allocation allowed) ----------------
__device__ __align__(16) float g_v1[256];
__device__ __align__(16) float g_v2[256];
__device__ float g_p1[128];
__device__ float g_p2[128];

// ---------------- prep: v1 = W@a1, v2 = W@a2, pos1/pos2 -----------------
// 1024 threads: v-dots by t<256, pos table dot parallelized over 8 f-segments.
__global__ void __launch_bounds__(1024) prep_kernel(const float* __restrict__ W,
                                                    const float* __restrict__ a) {
    __shared__ float v1s[256], v2s[256];
    __shared__ float a1s[256], a2s[256];
    __shared__ double invd[128];
    __shared__ float psum1[1024], psum2[1024];
    const int t = threadIdx.x;

    if (t < 256) { a1s[t] = a[t]; a2s[t] = a[256 + t]; }
    if (t < 128) invd[t] = pow(10000.0, -(double)(2 * t) / 256.0);
    __syncthreads();

    if (t < 256) {
        float acc1 = 0.f, acc2 = 0.f;
        const float4* Wv = (const float4*)(W + t * 256);
        const float4* A1 = (const float4*)a1s;
        const float4* A2 = (const float4*)a2s;
#pragma unroll 8
        for (int q = 0; q < 64; q++) {
            float4 w = Wv[q];
            float4 b1 = A1[q], b2 = A2[q];
            acc1 += w.x * b1.x + w.y * b1.y + w.z * b1.z + w.w * b1.w;
            acc2 += w.x * b2.x + w.y * b2.y + w.z * b2.z + w.w * b2.w;
        }
        v1s[t] = acc1; v2s[t] = acc2;
        g_v1[t] = acc1; g_v2[t] = acc2;
    }
    __syncthreads();

    // pos partials: thread handles n = t&127, f in [seg*32, seg*32+32), seg = t>>7
    {
        const int n = t & 127;
        const int seg = t >> 7;
        float p1 = 0.f, p2 = 0.f;
#pragma unroll
        for (int pp = 0; pp < 16; pp++) {
            const int p = seg * 16 + pp;             // pair index, f = 2p / 2p+1
            float angle = (float)((double)n * invd[p]);
            float s, c;
            sincosf(angle, &s, &c);
            p1 += s * v1s[2 * p] + c * v1s[2 * p + 1];
            p2 += s * v2s[2 * p] + c * v2s[2 * p + 1];
        }
        psum1[t] = p1; psum2[t] = p2;
    }
    __syncthreads();

    if (t < 128) {
        float p1 = 0.f, p2 = 0.f;
#pragma unroll
        for (int s = 0; s < 8; s++) { p1 += psum1[s * 128 + t]; p2 += psum2[s * 128 + t]; }
        g_p1[t] = 1000.0f * p1;
        g_p2[t] = 1000.0f * p2;
    }
}

// ---------------- fused main kernel: 1 CTA per batch --------------------
// Scale-invariant softmax: out[i,j] = mask * E[i,j] / S_j, where
//   rows i<64 : E = elt[2i + (j>=64)]   (elt = exp(leaky(s1[m]+s2[m])))
//   rows i>=64: E = elu[j]              (elu = exp(leaky(s1[2j%128]+s2[(2j+1)%128])))
__global__ void __launch_bounds__(256) gat_kernel(
    const float* __restrict__ src,
    const float* __restrict__ adj,
    float* __restrict__ out)
{
    __shared__ float s1s[128], s2s[128];
    __shared__ float elt[128], elu[128];
    __shared__ float red[256];

    const int b   = blockIdx.x;
    const int tid = threadIdx.x;
    const int w   = tid >> 5;
    const int l   = tid & 31;

    // -- phase A: s1[n] = src[b,n,:].v1 + pos1[n]  (8 warps x 16 rows) --
    const float4* v1p = (const float4*)g_v1;
    const float4* v2p = (const float4*)g_v2;
    float4 v1a = v1p[l], v1b = v1p[l + 32];
    float4 v2a = v2p[l], v2b = v2p[l + 32];

    const float4* sbase = (const float4*)(src + (size_t)b * 32768);
#pragma unroll 2
    for (int r = 0; r < 16; r++) {
        int n = w * 16 + r;
        float4 x0 = sbase[n * 64 + l];
        float4 x1 = sbase[n * 64 + 32 + l];
        float acc1 = x0.x * v1a.x + x0.y * v1a.y + x0.z * v1a.z + x0.w * v1a.w
                   + x1.x * v1b.x + x1.y * v1b.y + x1.z * v1b.z + x1.w * v1b.w;
        float acc2 = x0.x * v2a.x + x0.y * v2a.y + x0.z * v2a.z + x0.w * v2a.w
                   + x1.x * v2b.x + x1.y * v2b.y + x1.z * v2b.z + x1.w * v2b.w;
#pragma unroll
        for (int off = 16; off; off >>= 1) {
            acc1 += __shfl_xor_sync(0xFFFFFFFFu, acc1, off);
            acc2 += __shfl_xor_sync(0xFFFFFFFFu, acc2, off);
        }
        if (l == 0) {
            s1s[n] = acc1 + g_p1[n];
            s2s[n] = acc2 + g_p2[n];
        }
    }
    __syncthreads();

    // -- phase B: exp(leaky(t)), exp(leaky(u)) --
    if (tid < 128) {
        int m = tid;
        float t = s1s[m] + s2s[m];
        t = (t > 0.f) ? t : 0.2f * t;
        elt[m] = expf(t);
        float u = s1s[(2 * m) & 127] + s2s[(2 * m + 1) & 127];
        u = (u > 0.f) ? u : 0.2f * u;
        elu[m] = expf(u);
    }
    __syncthreads();

    // -- phase C: read adj column slice, build mask, accumulate S --
    const int j = tid & 127;
    const int h = tid >> 7;                       // h=0: rows 0..63, h=1: rows 64..127
    const float* adjb = adj + (size_t)b * 16384 + (size_t)(h << 13) + j;

    unsigned m0 = 0, m1 = 0;
    float S = 0.f;
    if (h == 0) {
        const int jhi = j >> 6;
#pragma unroll
        for (int ii = 0; ii < 32; ii++) {
            float av = __ldg(adjb + ii * 128);
            if (av > 0.f) { m0 |= 1u << ii; S += elt[2 * ii + jhi]; }
        }
#pragma unroll
        for (int ii = 0; ii < 32; ii++) {
            float av = __ldg(adjb + (32 + ii) * 128);
            if (av > 0.f) { m1 |= 1u << ii; S += elt[64 + 2 * ii + jhi]; }
        }
    } else {
#pragma unroll
        for (int ii = 0; ii < 32; ii++) {
            float av = __ldg(adjb + ii * 128);
            m0 |= (av > 0.f ? 1u : 0u) << ii;
        }
#pragma unroll
        for (int ii = 0; ii < 32; ii++) {
            float av = __ldg(adjb + (32 + ii) * 128);
            m1 |= (av > 0.f ? 1u : 0u) << ii;
        }
        S = (float)(__popc(m0) + __popc(m1)) * elu[j];
    }
    red[tid] = S;
    __syncthreads();
    const float Stot = red[j] + red[j + 128];
    // all-masked column: reference softmax of equal NEG values -> uniform 1/128
    const float inv = (Stot > 0.f) ? (1.0f / Stot) : 0.f;
    const float add = (Stot > 0.f) ? 0.f : 0.0078125f;

    // -- phase D: write-out (coalesced in j) --
    float* outp = out + (size_t)b * 16384 + (size_t)(h << 13) + j;
    if (h == 0) {
        const int jhi = j >> 6;
#pragma unroll
        for (int ii = 0; ii < 32; ii++) {
            float v = ((m0 >> ii) & 1u) ? elt[2 * ii + jhi] * inv : 0.f;
            outp[ii * 128] = v + add;
        }
#pragma unroll
        for (int ii = 0; ii < 32; ii++) {
            float v = ((m1 >> ii) & 1u) ? elt[64 + 2 * ii + jhi] * inv : 0.f;
            outp[(32 + ii) * 128] = v + add;
        }
    } else {
        const float c = elu[j] * inv;
#pragma unroll
        for (int ii = 0; ii < 32; ii++) {
            float v = ((m0 >> ii) & 1u) ? c : 0.f;
            outp[ii * 128] = v + add;
        }
#pragma unroll
        for (int ii = 0; ii < 32; ii++) {
            float v = ((m1 >> ii) & 1u) ? c : 0.f;
            outp[(32 + ii) * 128] = v + add;
        }
    }
}

// ---------------- launcher ----------------
extern "C" void kernel_launch(void* const* d_in, const int* in_sizes, int n_in,
                              void* d_out, int out_size) {
    const float* src = (const float*)d_in[0];   // (2048,128,256)
    const float* W   = (const float*)d_in[1];   // (256,256)
    const float* a   = (const float*)d_in[2];   // (512,1)
    const float* adj = (const float*)d_in[3];   // (2048,128,128)
    float* out = (float*)d_out;                 // (2048,128,128)

    prep_kernel<<<1, 1024>>>(W, a);
    gat_kernel<<<2048, 256>>>(src, adj, out);
}